// round 13
// baseline (speedup 1.0000x reference)
#include <cuda_runtime.h>
#include <cuda_bf16.h>
#include <math.h>
#include <stdint.h>

#define BB 64
#define CIN 64
#define T0 4096
#define HH 64
#define H 128
#define T1 2048
#define T2 1024
#define RH 64
#define DD 64
#define KCB 512
#define NN (BB*T2)

__device__ float g_h1[(size_t)BB*HH*T1];
__device__ float g_h2[(size_t)BB*H*T2];
__device__ float g_h3[(size_t)BB*H*T2];
__device__ float g_WcT[H*DD];
__device__ float g_bc[DD];
__device__ float g_cnorm[KCB];
__device__ int   g_hist[KCB];
__device__ float g_losssum;
__device__ __nv_bfloat16 g_ws3[3*128*384];
__device__ __nv_bfloat16 g_wr0[3*64*384];
__device__ __nv_bfloat16 g_wr1[3*64*384];

__device__ __forceinline__ void cpa16(void* d, const void* s, bool ok) {
    uint32_t da = (uint32_t)__cvta_generic_to_shared(d);
    asm volatile("cp.async.cg.shared.global [%0], [%1], 16, %2;" :: "r"(da), "l"(s), "r"(ok?16:0));
}
__device__ __forceinline__ void cpa4(void* d, const float* s) {
    uint32_t da = (uint32_t)__cvta_generic_to_shared(d);
    asm volatile("cp.async.ca.shared.global [%0], [%1], 4;" :: "r"(da), "l"(s));
}
__device__ __forceinline__ void cp_commit() { asm volatile("cp.async.commit_group;"); }
__device__ __forceinline__ void cp_wait0()  { asm volatile("cp.async.wait_group 0;"); }

__device__ __forceinline__ void bf3(float v, __nv_bfloat16& a, __nv_bfloat16& b, __nv_bfloat16& c) {
    a = __float2bfloat16(v); float r = v - __bfloat162float(a);
    b = __float2bfloat16(r); c = __float2bfloat16(r - __bfloat162float(b));
}
__device__ __forceinline__ void ldsm4(uint32_t* r, uint32_t a) {
    asm volatile("ldmatrix.sync.aligned.m8n8.x4.shared.b16 {%0,%1,%2,%3},[%4];"
        : "=r"(r[0]),"=r"(r[1]),"=r"(r[2]),"=r"(r[3]) : "r"(a));
}
__device__ __forceinline__ void ldsm2(uint32_t* r, uint32_t a) {
    asm volatile("ldmatrix.sync.aligned.m8n8.x2.shared.b16 {%0,%1},[%2];"
        : "=r"(r[0]),"=r"(r[1]) : "r"(a));
}
__device__ __forceinline__ void mmab(float* d, const uint32_t* a, const uint32_t* b) {
    asm volatile("mma.sync.aligned.m16n8k16.row.col.f32.bf16.bf16.f32 "
        "{%0,%1,%2,%3},{%4,%5,%6,%7},{%8,%9},{%0,%1,%2,%3};"
        : "+f"(d[0]),"+f"(d[1]),"+f"(d[2]),"+f"(d[3])
        : "r"(a[0]),"r"(a[1]),"r"(a[2]),"r"(a[3]),"r"(b[0]),"r"(b[1]));
}

__global__ void precompute_k(const float* __restrict__ wpq, const float* __restrict__ w_out,
                             const float* __restrict__ b_out, const float* __restrict__ bpq,
                             const float* __restrict__ cb)
{
    const int bid = blockIdx.x, tid = threadIdx.x;
    if (bid < 64) {
        __shared__ float wrow[64];
        if (tid < 64) wrow[tid] = wpq[bid*DD + tid];
        __syncthreads();
        float s = 0.f;
        #pragma unroll
        for (int d = 0; d < DD; d++) s = fmaf(wrow[d], w_out[d*H + tid], s);
        g_WcT[tid*DD + bid] = s;
    } else if (bid == 64) {
        if (tid < DD) {
            float s = bpq[tid];
            #pragma unroll
            for (int d = 0; d < DD; d++) s = fmaf(wpq[tid*DD + d], b_out[d], s);
            g_bc[tid] = s;
        }
        if (tid == 0) g_losssum = 0.f;
    } else {
        for (int k = tid; k < KCB; k += 128) {
            float s = 0.f;
            #pragma unroll
            for (int d = 0; d < DD; d++) { float c = cb[k*DD + d]; s = fmaf(c, c, s); }
            g_cnorm[k] = s; g_hist[k] = 0;
        }
    }
}

// weight bf16 3-split precompute (once; tiny)
__global__ void wsplit_k(const float* __restrict__ w3, const float* __restrict__ r0,
                         const float* __restrict__ r1)
{
    for (int idx = blockIdx.x*256 + threadIdx.x; idx < 98304; idx += gridDim.x*256) {
        const float* src; __nv_bfloat16* dst; int off, str;
        if (idx < 49152)      { src = w3; dst = g_ws3; off = idx;       str = 49152; }
        else if (idx < 73728) { src = r0; dst = g_wr0; off = idx-49152; str = 24576; }
        else                  { src = r1; dst = g_wr1; off = idx-73728; str = 24576; }
        __nv_bfloat16 a,b,c; bf3(src[off],a,b,c);
        dst[off]=a; dst[str+off]=b; dst[2*str+off]=c;
    }
}

// ---- K=4 S=2 conv (scalar, R10-proven) ----
#define S2_WC (8*4*64)
#define S2_XC (8*264)
__global__ void __launch_bounds__(256,4) convS2_k(
    const float* __restrict__ in, const float* __restrict__ w,
    const float* __restrict__ bias, float* __restrict__ out,
    int Cin, int Tin, int Cout, int Tout)
{
    extern __shared__ float sm[];
    float* swb = sm; float* sxb = sm + 2*S2_WC;
    const int tid = threadIdx.x, tslot = tid&15, cslot = tid>>4;
    const int t0 = blockIdx.x*128, co0 = blockIdx.y*64, b = blockIdx.z;

    float acc[4][8];
    #pragma unroll
    for (int c = 0; c < 4; c++) {
        float bv = bias[co0 + cslot*4 + c];
        #pragma unroll
        for (int j = 0; j < 8; j++) acc[c][j] = bv;
    }
    auto load_chunk = [&](int cc, int buf) {
        float* sx = sxb + buf*S2_XC;
        for (int idx = tid; idx < 8*66; idx += 256) {
            int ci = idx/66, q = idx - ci*66;
            int gb = 2*t0 - 4 + 4*q;
            bool ok = (gb >= 0) && (gb + 4 <= Tin);
            cpa16(&sx[ci*264 + 4*q], in + ((size_t)b*Cin + cc + ci)*Tin + (ok?gb:0), ok);
        }
        float* sw = swb + buf*S2_WC;
        for (int idx = tid; idx < 8*4*64; idx += 256) {
            int co = idx&63, r = idx>>6, ci = r>>2, k = r&3;
            cpa4(&sw[idx], &w[((size_t)(co0+co)*Cin + cc + ci)*4 + k]);
        }
    };
    const int nch = Cin>>3;
    load_chunk(0,0); cp_commit();
    for (int c = 0; c < nch; c++) {
        cp_wait0(); __syncthreads();
        if (c + 1 < nch) { load_chunk((c+1)<<3, (c+1)&1); cp_commit(); }
        const float* sx = sxb + (c&1)*S2_XC;
        const float* sw = swb + (c&1)*S2_WC;
        #pragma unroll 2
        for (int ci = 0; ci < 8; ci++) {
            float x[24];
            const float* xr = &sx[ci*264 + tslot*16];
            #pragma unroll
            for (int q = 0; q < 6; q++) { float4 v = *(const float4*)(xr+4*q); x[4*q]=v.x; x[4*q+1]=v.y; x[4*q+2]=v.z; x[4*q+3]=v.w; }
            #pragma unroll
            for (int k = 0; k < 4; k++) {
                float4 wv = *(const float4*)&sw[(ci*4+k)*64 + cslot*4];
                float wc[4] = {wv.x, wv.y, wv.z, wv.w};
                #pragma unroll
                for (int c4 = 0; c4 < 4; c4++)
                    #pragma unroll
                    for (int j = 0; j < 8; j++)
                        acc[c4][j] = fmaf(x[2*j+3+k], wc[c4], acc[c4][j]);
            }
        }
    }
    #pragma unroll
    for (int c = 0; c < 4; c++) {
        float4* op = (float4*)(out + ((size_t)b*Cout + co0 + cslot*4 + c)*Tout + t0 + tslot*8);
        op[0] = make_float4(fmaxf(acc[c][0],0.f), fmaxf(acc[c][1],0.f), fmaxf(acc[c][2],0.f), fmaxf(acc[c][3],0.f));
        op[1] = make_float4(fmaxf(acc[c][4],0.f), fmaxf(acc[c][5],0.f), fmaxf(acc[c][6],0.f), fmaxf(acc[c][7],0.f));
    }
}

// ---- HMMA K=3 conv: D[128t x 64co per block-y] = Xshift(bf16 3-split) @ W^T, 6 passes ----
#define XS_STR 72
#define WS_STR 392
template<bool RELU_IN, bool RELU_OUT, bool HAS_BIAS>
__global__ void __launch_bounds__(256) hmma3_k(
    const float* __restrict__ in, int wsel, const float* __restrict__ bias,
    float* __restrict__ out)
{
    extern __shared__ __align__(16) char smc[];
    float* sbias = (float*)smc;                                   // 256 B
    __nv_bfloat16* Ws = (__nv_bfloat16*)(smc + 256);              // 3*64*392
    __nv_bfloat16* Xs = (__nv_bfloat16*)(smc + 256 + 3*64*WS_STR*2);
    float* raw = (float*)(smc + 256 + 3*64*WS_STR*2 + 3*128*XS_STR*2);  // 23*136

    const int tid = threadIdx.x, t0 = blockIdx.x*128, co0 = blockIdx.y*64, b = blockIdx.z;
    const int Cout = gridDim.y*64;
    const __nv_bfloat16* ws = (wsel==0) ? g_ws3 : (wsel==1) ? g_wr0 : g_wr1;
    const int wstride = (wsel==0) ? 49152 : 24576;
    const uint32_t sWs = (uint32_t)__cvta_generic_to_shared(Ws);
    const uint32_t sXs = (uint32_t)__cvta_generic_to_shared(Xs);

    if (HAS_BIAS && tid < 64) sbias[tid] = bias[co0 + tid];
    for (int idx = tid; idx < 3*64*48; idx += 256) {   // resident W (full K=384)
        int s = idx/3072, rem = idx - s*3072, n = rem/48, q = rem - n*48;
        cpa16(Ws + (s*64 + n)*WS_STR + 8*q,
              ws + (size_t)s*wstride + (size_t)(co0+n)*384 + 8*q, true);
    }
    cp_commit();

    float acc[8][4];
    #pragma unroll
    for (int n = 0; n < 8; n++) { acc[n][0]=0.f; acc[n][1]=0.f; acc[n][2]=0.f; acc[n][3]=0.f; }
    const int wm = tid>>5, l = tid&31;

    #pragma unroll 1
    for (int c = 0; c < 6; c++) {
        const int r0 = 64*c, rlo = r0/3, rows = (r0+63)/3 - rlo + 1;
        __syncthreads();   // prior mma LDSMs + raw reads complete
        for (int idx = tid; idx < rows*34; idx += 256) {
            int cl = idx/34, q = idx - cl*34;
            int gb = t0 - 4 + 4*q;
            bool ok = (gb >= 0) && (gb + 4 <= T2);
            cpa16(raw + cl*136 + 4*q, in + ((size_t)b*H + rlo + cl)*T2 + (ok?gb:0), ok);
        }
        cp_commit(); cp_wait0();
        __syncthreads();
        for (int idx = tid; idx < 64*128; idx += 256) {   // Xshift[t][kr], 3 splits
            int kr = idx>>7, t = idx&127;
            int r = r0 + kr, ci = r/3, k = r - 3*ci;
            float v = raw[(ci-rlo)*136 + t + k + 3];
            if (RELU_IN) v = fmaxf(v, 0.f);
            __nv_bfloat16 x1,x2,x3; bf3(v,x1,x2,x3);
            int o = t*XS_STR + kr;
            Xs[o] = x1; Xs[128*XS_STR + o] = x2; Xs[2*128*XS_STR + o] = x3;
        }
        __syncthreads();

        const int SA[6]={0,0,1,0,1,2}, SBp[6]={0,1,0,2,1,0};
        #pragma unroll 1
        for (int p = 0; p < 6; p++) {
            uint32_t abase = sXs + (uint32_t)(SA[p]*128*XS_STR + (wm*16 + (l&15))*XS_STR + ((l>>4)&1)*8)*2;
            uint32_t bbase = sWs + (uint32_t)(SBp[p]*64*WS_STR + (l&7)*WS_STR + ((l>>3)&1)*8 + r0)*2;
            #pragma unroll
            for (int kt = 0; kt < 4; kt++) {
                uint32_t a[4]; ldsm4(a, abase + kt*32);
                #pragma unroll
                for (int nt = 0; nt < 8; nt++) {
                    uint32_t bb[2]; ldsm2(bb, bbase + (uint32_t)(nt*8*WS_STR)*2 + kt*32);
                    mmab(acc[nt], a, bb);
                }
            }
        }
    }

    // epilogue: d0,d1 -> row l/4; d2,d3 -> row l/4+8; cols 2(l&3)+{0,1}
    #pragma unroll
    for (int nt = 0; nt < 8; nt++) {
        int cr = nt*8 + 2*(l&3);
        int tr = t0 + wm*16 + (l>>2);
        float v0 = acc[nt][0], v1 = acc[nt][1], v2 = acc[nt][2], v3 = acc[nt][3];
        if (HAS_BIAS) { float b0 = sbias[cr], b1 = sbias[cr+1]; v0 += b0; v1 += b1; v2 += b0; v3 += b1; }
        if (RELU_OUT) { v0=fmaxf(v0,0.f); v1=fmaxf(v1,0.f); v2=fmaxf(v2,0.f); v3=fmaxf(v3,0.f); }
        float* o0 = out + ((size_t)b*Cout + co0 + cr)*T2 + tr;
        float* o1 = o0 + T2;
        o0[0] = v0; o1[0] = v1; o0[8] = v2; o1[8] = v3;
    }
}

// ---- 1x1 conv accumulate (R9-validated) ----
#define P1_SW (64*64)
#define P1_SX (64*132)
__global__ void __launch_bounds__(256,3) conv1x1acc_k(
    const float* __restrict__ in, const float* __restrict__ w, float* __restrict__ out)
{
    extern __shared__ float sm[];
    float* sw = sm; float* sx = sm + P1_SW;
    const int tid = threadIdx.x, tslot = tid&15, cslot = tid>>4;
    const int t0 = blockIdx.x*128, co0 = blockIdx.y*64, b = blockIdx.z;
    const int Cout = gridDim.y*64;

    for (int idx = tid; idx < 64*32; idx += 256) {
        int ci = idx>>5, q = idx&31;
        cpa16(&sx[ci*132 + 4*q], in + ((size_t)b*RH + ci)*T2 + t0 + 4*q, true);
    }
    for (int idx = tid; idx < 64*64; idx += 256) {
        int ci = idx>>6, co = idx&63;
        cpa4(&sw[ci*64 + co], &w[(size_t)(co0+co)*RH + ci]);
    }
    cp_commit(); cp_wait0();
    __syncthreads();

    float acc[4][8];
    #pragma unroll
    for (int c = 0; c < 4; c++)
        #pragma unroll
        for (int j = 0; j < 8; j++) acc[c][j] = 0.f;
    #pragma unroll 2
    for (int ci = 0; ci < RH; ci++) {
        float x[8];
        const float* xr = &sx[ci*132 + tslot*8];
        { float4 v = *(const float4*)(xr);   x[0]=v.x; x[1]=v.y; x[2]=v.z; x[3]=v.w; }
        { float4 v = *(const float4*)(xr+4); x[4]=v.x; x[5]=v.y; x[6]=v.z; x[7]=v.w; }
        float4 wv = *(const float4*)&sw[ci*64 + cslot*4];
        float wc[4] = {wv.x, wv.y, wv.z, wv.w};
        #pragma unroll
        for (int c = 0; c < 4; c++)
            #pragma unroll
            for (int j = 0; j < 8; j++) acc[c][j] = fmaf(x[j], wc[c], acc[c][j]);
    }
    #pragma unroll
    for (int c = 0; c < 4; c++) {
        float* op = out + ((size_t)b*Cout + co0 + cslot*4 + c)*T2 + t0 + tslot*8;
        float4 o0 = *(float4*)op, o1 = *((float4*)op + 1);
        *(float4*)op       = make_float4(o0.x+acc[c][0], o0.y+acc[c][1], o0.z+acc[c][2], o0.w+acc[c][3]);
        *((float4*)op + 1) = make_float4(o1.x+acc[c][4], o1.y+acc[c][5], o1.z+acc[c][6], o1.w+acc[c][7]);
    }
}

// ---- fused relu + Wc + transpose -> z_e ----
#define Z_SH (128*136)
#define Z_SW (128*64)
__global__ void __launch_bounds__(256) zfused_k(const float* __restrict__ h, float* __restrict__ ze)
{
    extern __shared__ float s[];
    float* sh = s; float* sw = s + Z_SH;
    const int tid = threadIdx.x, tslot = tid&15, cslot = tid>>4;
    const int t0 = blockIdx.x*128, b = blockIdx.z;

    for (int idx = tid; idx < 128*128; idx += 256) {
        int ci = idx>>7, t = idx&127;
        sh[ci*136 + t] = fmaxf(h[((size_t)b*H + ci)*T2 + t0 + t], 0.f);
    }
    for (int i = tid; i < (H*DD)/4; i += 256) ((float4*)sw)[i] = ((const float4*)g_WcT)[i];
    __syncthreads();

    float acc[4][8];
    #pragma unroll
    for (int c = 0; c < 4; c++) {
        float bv = g_bc[cslot*4 + c];
        #pragma unroll
        for (int j = 0; j < 8; j++) acc[c][j] = bv;
    }
    #pragma unroll 2
    for (int ch = 0; ch < H; ch++) {
        float x[8];
        const float* xr = &sh[ch*136 + tslot*8];
        { float4 v = *(const float4*)(xr);   x[0]=v.x; x[1]=v.y; x[2]=v.z; x[3]=v.w; }
        { float4 v = *(const float4*)(xr+4); x[4]=v.x; x[5]=v.y; x[6]=v.z; x[7]=v.w; }
        float4 wv = *(const float4*)&sw[ch*64 + cslot*4];
        float wc[4] = {wv.x, wv.y, wv.z, wv.w};
        #pragma unroll
        for (int c = 0; c < 4; c++)
            #pragma unroll
            for (int j = 0; j < 8; j++) acc[c][j] = fmaf(x[j], wc[c], acc[c][j]);
    }
    #pragma unroll
    for (int j = 0; j < 8; j++) {
        size_t n = (size_t)b*T2 + t0 + tslot*8 + j;
        float2* op = (float2*)(ze + n*DD + cslot*4);
        op[0] = make_float2(acc[0][j], acc[1][j]);
        op[1] = make_float2(acc[2][j], acc[3][j]);
    }
}

// ---- VQ distance-GEMM ----
#define VQ_SZ (64*136)
#define VQ_SC (64*136)
__global__ void __launch_bounds__(256) vqgemm_k(
    const float* __restrict__ ze, const float* __restrict__ cb,
    float* __restrict__ zq, float* __restrict__ enc, float* __restrict__ idxout)
{
    extern __shared__ float s[];
    float* szeT = s; float* scb = s + VQ_SZ; float* scn = scb + VQ_SC;
    int* sbk = (int*)(scn + KCB);
    const int tid = threadIdx.x, n0 = blockIdx.x*128, nslot = tid>>4, kslot = tid&15;

    for (int idx = tid; idx < 128*DD; idx += 256) {
        int n = idx>>6, d = idx&63;
        szeT[d*136 + n] = ze[(size_t)(n0+n)*DD + d];
    }
    for (int k = tid; k < KCB; k += 256) scn[k] = g_cnorm[k];
    __syncthreads();

    float best[8]; int bk[8];
    #pragma unroll
    for (int i = 0; i < 8; i++) { best[i] = 3.4e38f; bk[i] = 0; }

    for (int kc = 0; kc < KCB; kc += 128) {
        for (int idx = tid; idx < 128*DD; idx += 256) {
            int kk = idx>>6, d = idx&63;
            scb[d*136 + kk] = cb[(size_t)(kc+kk)*DD + d];
        }
        __syncthreads();
        float acc[8][8];
        #pragma unroll
        for (int i = 0; i < 8; i++)
            #pragma unroll
            for (int j = 0; j < 8; j++) acc[i][j] = 0.f;
        #pragma unroll 2
        for (int d = 0; d < DD; d++) {
            float fz[8], fc[8];
            const float* zr = &szeT[d*136 + nslot*8];
            { float4 v = *(const float4*)(zr);   fz[0]=v.x; fz[1]=v.y; fz[2]=v.z; fz[3]=v.w; }
            { float4 v = *(const float4*)(zr+4); fz[4]=v.x; fz[5]=v.y; fz[6]=v.z; fz[7]=v.w; }
            const float* cr = &scb[d*136 + kslot*8];
            { float4 v = *(const float4*)(cr);   fc[0]=v.x; fc[1]=v.y; fc[2]=v.z; fc[3]=v.w; }
            { float4 v = *(const float4*)(cr+4); fc[4]=v.x; fc[5]=v.y; fc[6]=v.z; fc[7]=v.w; }
            #pragma unroll
            for (int i = 0; i < 8; i++)
                #pragma unroll
                for (int j = 0; j < 8; j++) acc[i][j] = fmaf(fz[i], fc[j], acc[i][j]);
        }
        #pragma unroll
        for (int j = 0; j < 8; j++) {
            int kg = kc + kslot*8 + j;
            float cn = scn[kg];
            #pragma unroll
            for (int i = 0; i < 8; i++) {
                float dist = cn - 2.f*acc[i][j];
                if (dist < best[i]) { best[i] = dist; bk[i] = kg; }
            }
        }
        __syncthreads();
    }
    #pragma unroll
    for (int off = 8; off > 0; off >>= 1) {
        #pragma unroll
        for (int i = 0; i < 8; i++) {
            float ob = __shfl_down_sync(0xffffffffu, best[i], off, 16);
            int ok = __shfl_down_sync(0xffffffffu, bk[i], off, 16);
            if (ob < best[i] || (ob == best[i] && ok < bk[i])) { best[i] = ob; bk[i] = ok; }
        }
    }
    if (kslot == 0)
        #pragma unroll
        for (int i = 0; i < 8; i++) sbk[nslot*8 + i] = bk[i];
    __syncthreads();

    float part = 0.f;
    for (int idx = tid; idx < 128*DD; idx += 256) {
        int nl = idx>>6, d = idx&63;
        int kk = sbk[nl];
        float c = cb[(size_t)kk*DD + d];
        float f = szeT[d*136 + nl];
        zq[(size_t)(n0+nl)*DD + d] = c;
        float df = c - f;
        part = fmaf(df, df, part);
    }
    const float2 z2 = make_float2(0.f, 0.f);
    for (int r = 0; r < 128; r++) ((float2*)(enc + (size_t)(n0+r)*KCB))[tid] = z2;
    __syncthreads();
    if (tid < 128) {
        int kk = sbk[tid];
        idxout[n0 + tid] = (float)kk;
        enc[(size_t)(n0+tid)*KCB + kk] = 1.f;
        atomicAdd(&g_hist[kk], 1);
    }
    #pragma unroll
    for (int o = 16; o > 0; o >>= 1) part += __shfl_down_sync(0xffffffffu, part, o);
    __shared__ float wsum[8];
    if ((tid&31) == 0) wsum[tid>>5] = part;
    __syncthreads();
    if (tid < 8) {
        float v = wsum[tid];
        #pragma unroll
        for (int o = 4; o > 0; o >>= 1) v += __shfl_down_sync(0xffu, v, o);
        if (tid == 0) atomicAdd(&g_losssum, v);
    }
}

__global__ void fin_k(float* __restrict__ loss_out, float* __restrict__ perp_out)
{
    __shared__ float red[512];
    const int k = threadIdx.x;
    float p = (float)g_hist[k]*(1.0f/(float)NN);
    red[k] = p*logf(p + 1e-10f);
    __syncthreads();
    for (int s2 = 256; s2 > 0; s2 >>= 1) { if (k < s2) red[k] += red[k + s2]; __syncthreads(); }
    if (k == 0) {
        perp_out[0] = expf(-red[0]);
        loss_out[0] = 1.25f*g_losssum/(float)((size_t)NN*DD);
    }
}

extern "C" void kernel_launch(void* const* d_in, const int* in_sizes, int n_in,
                              void* d_out, int out_size)
{
    const float* x     = (const float*)d_in[0];
    const float* w1    = (const float*)d_in[1];
    const float* b1    = (const float*)d_in[2];
    const float* w2    = (const float*)d_in[3];
    const float* b2    = (const float*)d_in[4];
    const float* w3    = (const float*)d_in[5];
    const float* b3    = (const float*)d_in[6];
    const float* r0w1  = (const float*)d_in[7];
    const float* r0w2  = (const float*)d_in[8];
    const float* r1w1  = (const float*)d_in[9];
    const float* r1w2  = (const float*)d_in[10];
    const float* w_out = (const float*)d_in[11];
    const float* b_out = (const float*)d_in[12];
    const float* wpq   = (const float*)d_in[13];
    const float* bpq   = (const float*)d_in[14];
    const float* cb    = (const float*)d_in[15];

    float* outp = (float*)d_out;
    const size_t NZ = (size_t)NN*DD;
    float* o_loss = outp;
    float* o_zq   = outp + 1;
    float* o_perp = outp + 1 + NZ;
    float* o_ze   = outp + 2 + NZ;
    float* o_enc  = outp + 2 + 2*NZ;
    float* o_idx  = outp + 2 + 2*NZ + (size_t)NN*KCB;

    auto* kC3 = hmma3_k<false, false, true >;   // conv3 (bias)
    auto* kR3 = hmma3_k<true,  true,  false>;   // residual 3x3 (relu in/out)

    const int smem_S2 = 2*(S2_WC + S2_XC)*4;
    const int smem_H3 = 256 + 3*64*WS_STR*2 + 3*128*XS_STR*2 + 23*136*4;  // 218,592
    const int smem_P1 = (P1_SW + P1_SX)*4;
    const int z_smem  = (Z_SH + Z_SW)*4;
    const int vq_smem = (VQ_SZ + VQ_SC + KCB)*4 + 128*4;

    static int attr_done = 0;
    if (!attr_done) {
        cudaFuncSetAttribute(convS2_k,     cudaFuncAttributeMaxDynamicSharedMemorySize, smem_S2);
        cudaFuncSetAttribute(kC3,          cudaFuncAttributeMaxDynamicSharedMemorySize, smem_H3);
        cudaFuncSetAttribute(kR3,          cudaFuncAttributeMaxDynamicSharedMemorySize, smem_H3);
        cudaFuncSetAttribute(conv1x1acc_k, cudaFuncAttributeMaxDynamicSharedMemorySize, smem_P1);
        cudaFuncSetAttribute(zfused_k,     cudaFuncAttributeMaxDynamicSharedMemorySize, z_smem);
        cudaFuncSetAttribute(vqgemm_k,     cudaFuncAttributeMaxDynamicSharedMemorySize, vq_smem);
        attr_done = 1;
    }

    precompute_k<<<66, 128>>>(wpq, w_out, b_out, bpq, cb);
    wsplit_k<<<96, 256>>>(w3, r0w1, r1w1);

    convS2_k<<<dim3(16, 1, BB), 256, smem_S2>>>(x,    w1, b1, g_h1, CIN, T0, HH, T1);
    convS2_k<<<dim3(8,  2, BB), 256, smem_S2>>>(g_h1, w2, b2, g_h2, HH,  T1, H,  T2);

    kC3<<<dim3(8, 2, BB), 256, smem_H3>>>(g_h2, 0, b3, g_h3);

    kR3<<<dim3(8, 1, BB), 256, smem_H3>>>(g_h3, 1, nullptr, g_h1);
    conv1x1acc_k<<<dim3(8, 2, BB), 256, smem_P1>>>(g_h1, r0w2, g_h3);
    kR3<<<dim3(8, 1, BB), 256, smem_H3>>>(g_h3, 2, nullptr, g_h1);
    conv1x1acc_k<<<dim3(8, 2, BB), 256, smem_P1>>>(g_h1, r1w2, g_h3);

    zfused_k<<<dim3(8, 1, BB), 256, z_smem>>>(g_h3, o_ze);

    vqgemm_k<<<NN/128, 256, vq_smem>>>(o_ze, cb, o_zq, o_enc, o_idx);

    fin_k<<<1, 512>>>(o_loss, o_perp);
}

// round 14
// speedup vs baseline: 1.2555x; 1.2555x over previous
#include <cuda_runtime.h>
#include <math.h>
#include <stdint.h>

#define BB 64
#define CIN 64
#define T0 4096
#define HH 64
#define H 128
#define T1 2048
#define T2 1024
#define RH 64
#define DD 64
#define KCB 512
#define NN (BB*T2)

__device__ float g_h1[(size_t)BB*HH*T1];
__device__ float g_h2[(size_t)BB*H*T2];
__device__ float g_h3[(size_t)BB*H*T2];
__device__ float g_WcT[H*DD];
__device__ float g_bc[DD];
__device__ float g_cnorm[KCB];
__device__ int   g_hist[KCB];
__device__ float g_losssum;

__device__ __forceinline__ void cpa16(void* d, const float* s, bool ok) {
    uint32_t da = (uint32_t)__cvta_generic_to_shared(d);
    asm volatile("cp.async.cg.shared.global [%0], [%1], 16, %2;" :: "r"(da), "l"(s), "r"(ok?16:0));
}
__device__ __forceinline__ void cpa4(void* d, const float* s) {
    uint32_t da = (uint32_t)__cvta_generic_to_shared(d);
    asm volatile("cp.async.ca.shared.global [%0], [%1], 4;" :: "r"(da), "l"(s));
}
__device__ __forceinline__ void cp_commit() { asm volatile("cp.async.commit_group;"); }
__device__ __forceinline__ void cp_wait0()  { asm volatile("cp.async.wait_group 0;"); }

__global__ void precompute_k(const float* __restrict__ wpq, const float* __restrict__ w_out,
                             const float* __restrict__ b_out, const float* __restrict__ bpq,
                             const float* __restrict__ cb)
{
    const int bid = blockIdx.x, tid = threadIdx.x;
    if (bid < 64) {
        __shared__ float wrow[64];
        if (tid < 64) wrow[tid] = wpq[bid*DD + tid];
        __syncthreads();
        float s = 0.f;
        #pragma unroll
        for (int d = 0; d < DD; d++) s = fmaf(wrow[d], w_out[d*H + tid], s);
        g_WcT[tid*DD + bid] = s;
    } else if (bid == 64) {
        if (tid < DD) {
            float s = bpq[tid];
            #pragma unroll
            for (int d = 0; d < DD; d++) s = fmaf(wpq[tid*DD + d], b_out[d], s);
            g_bc[tid] = s;
        }
        if (tid == 0) g_losssum = 0.f;
    } else {
        for (int k = tid; k < KCB; k += 128) {
            float s = 0.f;
            #pragma unroll
            for (int d = 0; d < DD; d++) { float c = cb[k*DD + d]; s = fmaf(c, c, s); }
            g_cnorm[k] = s; g_hist[k] = 0;
        }
    }
}

// ---- K=4 S=2 conv + bias + relu (R10-proven) ----
#define S2_WC (8*4*64)
#define S2_XC (8*264)
__global__ void __launch_bounds__(256,4) convS2_k(
    const float* __restrict__ in, const float* __restrict__ w,
    const float* __restrict__ bias, float* __restrict__ out,
    int Cin, int Tin, int Cout, int Tout)
{
    extern __shared__ float sm[];
    float* swb = sm; float* sxb = sm + 2*S2_WC;
    const int tid = threadIdx.x, tslot = tid&15, cslot = tid>>4;
    const int t0 = blockIdx.x*128, co0 = blockIdx.y*64, b = blockIdx.z;

    float acc[4][8];
    #pragma unroll
    for (int c = 0; c < 4; c++) {
        float bv = bias[co0 + cslot*4 + c];
        #pragma unroll
        for (int j = 0; j < 8; j++) acc[c][j] = bv;
    }
    auto load_chunk = [&](int cc, int buf) {
        float* sx = sxb + buf*S2_XC;
        for (int idx = tid; idx < 8*66; idx += 256) {
            int ci = idx/66, q = idx - ci*66;
            int gb = 2*t0 - 4 + 4*q;
            bool ok = (gb >= 0) && (gb + 4 <= Tin);
            cpa16(&sx[ci*264 + 4*q], in + ((size_t)b*Cin + cc + ci)*Tin + (ok?gb:0), ok);
        }
        float* sw = swb + buf*S2_WC;
        for (int idx = tid; idx < 8*4*64; idx += 256) {
            int co = idx&63, r = idx>>6, ci = r>>2, k = r&3;
            cpa4(&sw[idx], &w[((size_t)(co0+co)*Cin + cc + ci)*4 + k]);
        }
    };
    const int nch = Cin>>3;
    load_chunk(0,0); cp_commit();
    for (int c = 0; c < nch; c++) {
        cp_wait0(); __syncthreads();
        if (c + 1 < nch) { load_chunk((c+1)<<3, (c+1)&1); cp_commit(); }
        const float* sx = sxb + (c&1)*S2_XC;
        const float* sw = swb + (c&1)*S2_WC;
        #pragma unroll 2
        for (int ci = 0; ci < 8; ci++) {
            float x[24];
            const float* xr = &sx[ci*264 + tslot*16];
            #pragma unroll
            for (int q = 0; q < 6; q++) { float4 v = *(const float4*)(xr+4*q); x[4*q]=v.x; x[4*q+1]=v.y; x[4*q+2]=v.z; x[4*q+3]=v.w; }
            #pragma unroll
            for (int k = 0; k < 4; k++) {
                float4 wv = *(const float4*)&sw[(ci*4+k)*64 + cslot*4];
                float wc[4] = {wv.x, wv.y, wv.z, wv.w};
                #pragma unroll
                for (int c4 = 0; c4 < 4; c4++)
                    #pragma unroll
                    for (int j = 0; j < 8; j++)
                        acc[c4][j] = fmaf(x[2*j+3+k], wc[c4], acc[c4][j]);
            }
        }
    }
    #pragma unroll
    for (int c = 0; c < 4; c++) {
        float4* op = (float4*)(out + ((size_t)b*Cout + co0 + cslot*4 + c)*Tout + t0 + tslot*8);
        op[0] = make_float4(fmaxf(acc[c][0],0.f), fmaxf(acc[c][1],0.f), fmaxf(acc[c][2],0.f), fmaxf(acc[c][3],0.f));
        op[1] = make_float4(fmaxf(acc[c][4],0.f), fmaxf(acc[c][5],0.f), fmaxf(acc[c][6],0.f), fmaxf(acc[c][7],0.f));
    }
}

// ---- K=3 S=1 conv + bias (R10-proven) ----
#define K3_WC (8*3*64)
#define K3_XC (8*136)
__global__ void __launch_bounds__(256,4) convS1_k(
    const float* __restrict__ in, const float* __restrict__ w,
    const float* __restrict__ bias, float* __restrict__ out,
    int Cin, int Cout)
{
    extern __shared__ float sm[];
    float* swb = sm; float* sxb = sm + 2*K3_WC;
    const int tid = threadIdx.x, tslot = tid&15, cslot = tid>>4;
    const int t0 = blockIdx.x*128, co0 = blockIdx.y*64, b = blockIdx.z;

    float acc[4][8];
    #pragma unroll
    for (int c = 0; c < 4; c++) {
        float bv = bias[co0 + cslot*4 + c];
        #pragma unroll
        for (int j = 0; j < 8; j++) acc[c][j] = bv;
    }
    auto load_chunk = [&](int cc, int buf) {
        float* sx = sxb + buf*K3_XC;
        for (int idx = tid; idx < 8*34; idx += 256) {
            int ci = idx/34, q = idx - ci*34;
            int gb = t0 - 4 + 4*q;
            bool ok = (gb >= 0) && (gb + 4 <= T2);
            cpa16(&sx[ci*136 + 4*q], in + ((size_t)b*Cin + cc + ci)*T2 + (ok?gb:0), ok);
        }
        float* sw = swb + buf*K3_WC;
        for (int idx = tid; idx < 8*3*64; idx += 256) {
            int co = idx&63, r = idx>>6, ci = r/3, k = r - ci*3;
            cpa4(&sw[idx], &w[((size_t)(co0+co)*Cin + cc + ci)*3 + k]);
        }
    };
    const int nch = Cin>>3;
    load_chunk(0,0); cp_commit();
    for (int c = 0; c < nch; c++) {
        cp_wait0(); __syncthreads();
        if (c + 1 < nch) { load_chunk((c+1)<<3, (c+1)&1); cp_commit(); }
        const float* sx = sxb + (c&1)*K3_XC;
        const float* sw = swb + (c&1)*K3_WC;
        #pragma unroll 2
        for (int ci = 0; ci < 8; ci++) {
            float x[16];
            const float* xr = &sx[ci*136 + tslot*8];
            #pragma unroll
            for (int q = 0; q < 4; q++) { float4 v = *(const float4*)(xr+4*q); x[4*q]=v.x; x[4*q+1]=v.y; x[4*q+2]=v.z; x[4*q+3]=v.w; }
            #pragma unroll
            for (int k = 0; k < 3; k++) {
                float4 wv = *(const float4*)&sw[(ci*3+k)*64 + cslot*4];
                float wc[4] = {wv.x, wv.y, wv.z, wv.w};
                #pragma unroll
                for (int c4 = 0; c4 < 4; c4++)
                    #pragma unroll
                    for (int j = 0; j < 8; j++)
                        acc[c4][j] = fmaf(x[j+3+k], wc[c4], acc[c4][j]);
            }
        }
    }
    #pragma unroll
    for (int c = 0; c < 4; c++) {
        float4* op = (float4*)(out + ((size_t)b*Cout + co0 + cslot*4 + c)*T2 + t0 + tslot*8);
        op[0] = make_float4(acc[c][0], acc[c][1], acc[c][2], acc[c][3]);
        op[1] = make_float4(acc[c][4], acc[c][5], acc[c][6], acc[c][7]);
    }
}

// ---- fused residual block (R10-proven) ----
#define RB_SH  (128*136)
#define RB_STA (64*136)
#define RB_WC  (16*3*64)
#define RB_SW  (64*132)
__global__ void __launch_bounds__(512) resblock_k(
    const float* __restrict__ in, const float* __restrict__ wa,
    const float* __restrict__ wb, float* __restrict__ out)
{
    extern __shared__ float s[];
    float* sh = s; float* sta = s + RB_SH; float* sw = sta + RB_STA;
    const int tid = threadIdx.x, t0 = blockIdx.x*128, b = blockIdx.z, tslot = tid&15;

    auto loadW = [&](int cc, int buf) {
        float* d = sw + buf*RB_WC;
        for (int idx = tid; idx < 16*3*64; idx += 512) {
            int mid = idx&63, r = idx>>6, ci = r/3, k = r - ci*3;
            cpa4(&d[idx], &wa[((size_t)mid*H + cc + ci)*3 + k]);
        }
    };
    loadW(0,0); cp_commit();
    for (int idx = tid; idx < 128*130; idx += 512) {
        int ci = idx/130, p = idx - ci*130;
        int g = t0 - 1 + p;
        sh[ci*136 + p] = (g >= 0 && g < T2) ? fmaxf(in[((size_t)b*H + ci)*T2 + g], 0.f) : 0.f;
    }
    {
        const int mslot = tid>>4;
        float acc[2][8];
        #pragma unroll
        for (int c = 0; c < 2; c++)
            #pragma unroll
            for (int j = 0; j < 8; j++) acc[c][j] = 0.f;
        for (int ch = 0; ch < 8; ch++) {
            cp_wait0(); __syncthreads();
            if (ch + 1 < 8) { loadW((ch+1)*16, (ch+1)&1); cp_commit(); }
            const float* swc = sw + (ch&1)*RB_WC;
            const int cc = ch*16;
            #pragma unroll 2
            for (int ci = 0; ci < 16; ci++) {
                float x[10];
                const float* xr = &sh[(cc+ci)*136 + tslot*8];
                { float4 v = *(const float4*)(xr);   x[0]=v.x; x[1]=v.y; x[2]=v.z; x[3]=v.w; }
                { float4 v = *(const float4*)(xr+4); x[4]=v.x; x[5]=v.y; x[6]=v.z; x[7]=v.w; }
                { float2 v = *(const float2*)(xr+8); x[8]=v.x; x[9]=v.y; }
                #pragma unroll
                for (int k = 0; k < 3; k++) {
                    float2 wv = *(const float2*)&swc[(ci*3+k)*64 + mslot*2];
                    #pragma unroll
                    for (int j = 0; j < 8; j++) {
                        acc[0][j] = fmaf(x[j+k], wv.x, acc[0][j]);
                        acc[1][j] = fmaf(x[j+k], wv.y, acc[1][j]);
                    }
                }
            }
        }
        __syncthreads();
        #pragma unroll
        for (int c = 0; c < 2; c++)
            #pragma unroll
            for (int jp = 0; jp < 4; jp++)
                *(float2*)&sta[(mslot*2+c)*136 + tslot*8 + 2*jp] =
                    make_float2(fmaxf(acc[c][2*jp],0.f), fmaxf(acc[c][2*jp+1],0.f));
    }
    __syncthreads();
    for (int idx = tid; idx < H*RH; idx += 512) {
        int co = idx>>6, mid = idx&63;
        sw[mid*132 + co] = wb[idx];
    }
    __syncthreads();
    {
        const int cslot = tid>>4;
        float acc[4][8];
        #pragma unroll
        for (int c = 0; c < 4; c++)
            #pragma unroll
            for (int j = 0; j < 8; j++) acc[c][j] = 0.f;
        #pragma unroll 2
        for (int mid = 0; mid < RH; mid++) {
            float x[8];
            const float* xr = &sta[mid*136 + tslot*8];
            { float4 v = *(const float4*)(xr);   x[0]=v.x; x[1]=v.y; x[2]=v.z; x[3]=v.w; }
            { float4 v = *(const float4*)(xr+4); x[4]=v.x; x[5]=v.y; x[6]=v.z; x[7]=v.w; }
            float4 wv = *(const float4*)&sw[mid*132 + cslot*4];
            float wc[4] = {wv.x, wv.y, wv.z, wv.w};
            #pragma unroll
            for (int c = 0; c < 4; c++)
                #pragma unroll
                for (int j = 0; j < 8; j++) acc[c][j] = fmaf(x[j], wc[c], acc[c][j]);
        }
        #pragma unroll
        for (int c = 0; c < 4; c++) {
            int co = cslot*4 + c;
            const float4* ip = (const float4*)(in + ((size_t)b*H + co)*T2 + t0 + tslot*8);
            float4 r0 = ip[0], r1 = ip[1];
            float4* op = (float4*)(out + ((size_t)b*H + co)*T2 + t0 + tslot*8);
            op[0] = make_float4(r0.x+acc[c][0], r0.y+acc[c][1], r0.z+acc[c][2], r0.w+acc[c][3]);
            op[1] = make_float4(r1.x+acc[c][4], r1.y+acc[c][5], r1.z+acc[c][6], r1.w+acc[c][7]);
        }
    }
}

// ---- FUSED: relu + Wc projection -> z_e  +  VQ (distance GEMM, argmin, outputs) ----
// smem: region A = 128x136 f32 (h tile; later aliased: szeT 64x136 then scb 64x136 at +RB? no—layout below)
// phase1: sh[128][136] + sw[128*64]; phase2 (alias): szeT = s (64*136), scb = s + 64*136; scn/sbk in sw region.
#define ZV_SH (128*136)
#define ZV_SW (128*64)
__global__ void __launch_bounds__(256) zvq_k(
    const float* __restrict__ h, const float* __restrict__ cb,
    float* __restrict__ ze, float* __restrict__ zq,
    float* __restrict__ enc, float* __restrict__ idxout)
{
    extern __shared__ float s[];
    float* sh  = s;               // phase1 h tile
    float* sw  = s + ZV_SH;       // phase1 WcT
    float* szeT = s;              // phase2 alias: [d64][136]
    float* scb  = s + 64*136;     // phase2 alias: [d64][136]
    float* scn  = sw;             // phase2: 512 norms in sw region
    int*   sbk  = (int*)(sw + KCB);

    const int tid = threadIdx.x, tslot = tid&15, cslot = tid>>4;
    const int t0 = blockIdx.x*128, b = blockIdx.z;
    const int n0 = b*T2 + t0;

    for (int idx = tid; idx < 128*128; idx += 256) {
        int ci = idx>>7, t = idx&127;
        sh[ci*136 + t] = fmaxf(h[((size_t)b*H + ci)*T2 + t0 + t], 0.f);
    }
    for (int i = tid; i < (H*DD)/4; i += 256) ((float4*)sw)[i] = ((const float4*)g_WcT)[i];
    __syncthreads();

    float acc[4][8];
    #pragma unroll
    for (int c = 0; c < 4; c++) {
        float bv = g_bc[cslot*4 + c];
        #pragma unroll
        for (int j = 0; j < 8; j++) acc[c][j] = bv;
    }
    #pragma unroll 2
    for (int ch = 0; ch < H; ch++) {
        float x[8];
        const float* xr = &sh[ch*136 + tslot*8];
        { float4 v = *(const float4*)(xr);   x[0]=v.x; x[1]=v.y; x[2]=v.z; x[3]=v.w; }
        { float4 v = *(const float4*)(xr+4); x[4]=v.x; x[5]=v.y; x[6]=v.z; x[7]=v.w; }
        float4 wv = *(const float4*)&sw[ch*64 + cslot*4];
        float wc[4] = {wv.x, wv.y, wv.z, wv.w};
        #pragma unroll
        for (int c = 0; c < 4; c++)
            #pragma unroll
            for (int j = 0; j < 8; j++) acc[c][j] = fmaf(x[j], wc[c], acc[c][j]);
    }

    // write z_e to global + stage into szeT alias (sh dead after this barrier)
    __syncthreads();
    #pragma unroll
    for (int j = 0; j < 8; j++) {
        size_t n = (size_t)n0 + tslot*8 + j;
        float2* op = (float2*)(ze + n*DD + cslot*4);
        op[0] = make_float2(acc[0][j], acc[1][j]);
        op[1] = make_float2(acc[2][j], acc[3][j]);
        #pragma unroll
        for (int c = 0; c < 4; c++)
            szeT[(cslot*4 + c)*136 + tslot*8 + j] = acc[c][j];
    }
    for (int k = tid; k < KCB; k += 256) scn[k] = g_cnorm[k];
    __syncthreads();

    // VQ distance GEMM (R10-proven): 8n x 8k per thread, 128k chunks
    const int nslot = tid>>4, kslot = tid&15;
    float best[8]; int bk[8];
    #pragma unroll
    for (int i = 0; i < 8; i++) { best[i] = 3.4e38f; bk[i] = 0; }

    for (int kc = 0; kc < KCB; kc += 128) {
        for (int idx = tid; idx < 128*DD; idx += 256) {
            int kk = idx>>6, d = idx&63;
            scb[d*136 + kk] = cb[(size_t)(kc+kk)*DD + d];
        }
        __syncthreads();
        float a2[8][8];
        #pragma unroll
        for (int i = 0; i < 8; i++)
            #pragma unroll
            for (int j = 0; j < 8; j++) a2[i][j] = 0.f;
        #pragma unroll 2
        for (int d = 0; d < DD; d++) {
            float fz[8], fc[8];
            const float* zr = &szeT[d*136 + nslot*8];
            { float4 v = *(const float4*)(zr);   fz[0]=v.x; fz[1]=v.y; fz[2]=v.z; fz[3]=v.w; }
            { float4 v = *(const float4*)(zr+4); fz[4]=v.x; fz[5]=v.y; fz[6]=v.z; fz[7]=v.w; }
            const float* cr = &scb[d*136 + kslot*8];
            { float4 v = *(const float4*)(cr);   fc[0]=v.x; fc[1]=v.y; fc[2]=v.z; fc[3]=v.w; }
            { float4 v = *(const float4*)(cr+4); fc[4]=v.x; fc[5]=v.y; fc[6]=v.z; fc[7]=v.w; }
            #pragma unroll
            for (int i = 0; i < 8; i++)
                #pragma unroll
                for (int j = 0; j < 8; j++) a2[i][j] = fmaf(fz[i], fc[j], a2[i][j]);
        }
        #pragma unroll
        for (int j = 0; j < 8; j++) {
            int kg = kc + kslot*8 + j;
            float cn = scn[kg];
            #pragma unroll
            for (int i = 0; i < 8; i++) {
                float dist = cn - 2.f*a2[i][j];
                if (dist < best[i]) { best[i] = dist; bk[i] = kg; }
            }
        }
        __syncthreads();
    }
    #pragma unroll
    for (int off = 8; off > 0; off >>= 1) {
        #pragma unroll
        for (int i = 0; i < 8; i++) {
            float ob = __shfl_down_sync(0xffffffffu, best[i], off, 16);
            int ok = __shfl_down_sync(0xffffffffu, bk[i], off, 16);
            if (ob < best[i] || (ob == best[i] && ok < bk[i])) { best[i] = ob; bk[i] = ok; }
        }
    }
    if (kslot == 0)
        #pragma unroll
        for (int i = 0; i < 8; i++) sbk[nslot*8 + i] = bk[i];
    __syncthreads();

    float part = 0.f;
    for (int idx = tid; idx < 128*DD; idx += 256) {
        int nl = idx>>6, d = idx&63;
        int kk = sbk[nl];
        float c = cb[(size_t)kk*DD + d];
        float f = szeT[d*136 + nl];
        zq[(size_t)(n0+nl)*DD + d] = c;
        float df = c - f;
        part = fmaf(df, df, part);
    }
    const float2 z2 = make_float2(0.f, 0.f);
    for (int r = 0; r < 128; r++) ((float2*)(enc + (size_t)(n0+r)*KCB))[tid] = z2;
    __syncthreads();
    if (tid < 128) {
        int kk = sbk[tid];
        idxout[n0 + tid] = (float)kk;
        enc[(size_t)(n0+tid)*KCB + kk] = 1.f;
        atomicAdd(&g_hist[kk], 1);
    }
    #pragma unroll
    for (int o = 16; o > 0; o >>= 1) part += __shfl_down_sync(0xffffffffu, part, o);
    __shared__ float wsum[8];
    if ((tid&31) == 0) wsum[tid>>5] = part;
    __syncthreads();
    if (tid < 8) {
        float v = wsum[tid];
        #pragma unroll
        for (int o = 4; o > 0; o >>= 1) v += __shfl_down_sync(0xffu, v, o);
        if (tid == 0) atomicAdd(&g_losssum, v);
    }
}

__global__ void fin_k(float* __restrict__ loss_out, float* __restrict__ perp_out)
{
    __shared__ float red[512];
    const int k = threadIdx.x;
    float p = (float)g_hist[k]*(1.0f/(float)NN);
    red[k] = p*logf(p + 1e-10f);
    __syncthreads();
    for (int s2 = 256; s2 > 0; s2 >>= 1) { if (k < s2) red[k] += red[k + s2]; __syncthreads(); }
    if (k == 0) {
        perp_out[0] = expf(-red[0]);
        loss_out[0] = 1.25f*g_losssum/(float)((size_t)NN*DD);
    }
}

extern "C" void kernel_launch(void* const* d_in, const int* in_sizes, int n_in,
                              void* d_out, int out_size)
{
    const float* x     = (const float*)d_in[0];
    const float* w1    = (const float*)d_in[1];
    const float* b1    = (const float*)d_in[2];
    const float* w2    = (const float*)d_in[3];
    const float* b2    = (const float*)d_in[4];
    const float* w3    = (const float*)d_in[5];
    const float* b3    = (const float*)d_in[6];
    const float* r0w1  = (const float*)d_in[7];
    const float* r0w2  = (const float*)d_in[8];
    const float* r1w1  = (const float*)d_in[9];
    const float* r1w2  = (const float*)d_in[10];
    const float* w_out = (const float*)d_in[11];
    const float* b_out = (const float*)d_in[12];
    const float* wpq   = (const float*)d_in[13];
    const float* bpq   = (const float*)d_in[14];
    const float* cb    = (const float*)d_in[15];

    float* outp = (float*)d_out;
    const size_t NZ = (size_t)NN*DD;
    float* o_loss = outp;
    float* o_zq   = outp + 1;
    float* o_perp = outp + 1 + NZ;
    float* o_ze   = outp + 2 + NZ;
    float* o_enc  = outp + 2 + 2*NZ;
    float* o_idx  = outp + 2 + 2*NZ + (size_t)NN*KCB;

    const int smem_S2 = 2*(S2_WC + S2_XC)*4;
    const int smem_K3 = 2*(K3_WC + K3_XC)*4;
    const int res_smem = (RB_SH + RB_STA + RB_SW)*4;
    const int zv_smem = (ZV_SH + ZV_SW)*4;   // 102,400

    static int attr_done = 0;
    if (!attr_done) {
        cudaFuncSetAttribute(convS2_k,   cudaFuncAttributeMaxDynamicSharedMemorySize, smem_S2);
        cudaFuncSetAttribute(convS1_k,   cudaFuncAttributeMaxDynamicSharedMemorySize, smem_K3);
        cudaFuncSetAttribute(resblock_k, cudaFuncAttributeMaxDynamicSharedMemorySize, res_smem);
        cudaFuncSetAttribute(zvq_k,      cudaFuncAttributeMaxDynamicSharedMemorySize, zv_smem);
        attr_done = 1;
    }

    precompute_k<<<66, 128>>>(wpq, w_out, b_out, bpq, cb);

    convS2_k<<<dim3(16, 1, BB), 256, smem_S2>>>(x,    w1, b1, g_h1, CIN, T0, HH, T1);
    convS2_k<<<dim3(8,  2, BB), 256, smem_S2>>>(g_h1, w2, b2, g_h2, HH,  T1, H,  T2);
    convS1_k<<<dim3(8,  2, BB), 256, smem_K3>>>(g_h2, w3, b3, g_h3, H, H);

    resblock_k<<<dim3(8, 1, BB), 512, res_smem>>>(g_h3, r0w1, r0w2, g_h2);
    resblock_k<<<dim3(8, 1, BB), 512, res_smem>>>(g_h2, r1w1, r1w2, g_h3);

    zvq_k<<<dim3(8, 1, BB), 256, zv_smem>>>(g_h3, cb, o_ze, o_zq, o_enc, o_idx);

    fin_k<<<1, 512>>>(o_loss, o_perp);
}

// round 15
// speedup vs baseline: 1.6076x; 1.2805x over previous
#include <cuda_runtime.h>
#include <math.h>
#include <stdint.h>

#define BB 64
#define CIN 64
#define T0 4096
#define HH 64
#define H 128
#define T1 2048
#define T2 1024
#define RH 64
#define DD 64
#define KCB 512
#define NN (BB*T2)

__device__ float g_h1[(size_t)BB*HH*T1];
__device__ float g_h2[(size_t)BB*H*T2];
__device__ float g_h3[(size_t)BB*H*T2];
__device__ float g_WcT[H*DD];
__device__ float g_bc[DD];
__device__ float g_cnorm[KCB];
__device__ int   g_hist[KCB];
__device__ float g_losssum;

__device__ __forceinline__ void cpa16(void* d, const float* s, bool ok) {
    uint32_t da = (uint32_t)__cvta_generic_to_shared(d);
    asm volatile("cp.async.cg.shared.global [%0], [%1], 16, %2;" :: "r"(da), "l"(s), "r"(ok?16:0));
}
__device__ __forceinline__ void cpa4(void* d, const float* s) {
    uint32_t da = (uint32_t)__cvta_generic_to_shared(d);
    asm volatile("cp.async.ca.shared.global [%0], [%1], 4;" :: "r"(da), "l"(s));
}
__device__ __forceinline__ void cp_commit() { asm volatile("cp.async.commit_group;"); }
__device__ __forceinline__ void cp_wait0()  { asm volatile("cp.async.wait_group 0;"); }
__device__ __forceinline__ void cp_wait1()  { asm volatile("cp.async.wait_group 1;"); }

__global__ void precompute_k(const float* __restrict__ wpq, const float* __restrict__ w_out,
                             const float* __restrict__ b_out, const float* __restrict__ bpq,
                             const float* __restrict__ cb)
{
    const int bid = blockIdx.x, tid = threadIdx.x;
    if (bid < 64) {
        __shared__ float wrow[64];
        if (tid < 64) wrow[tid] = wpq[bid*DD + tid];
        __syncthreads();
        float s = 0.f;
        #pragma unroll
        for (int d = 0; d < DD; d++) s = fmaf(wrow[d], w_out[d*H + tid], s);
        g_WcT[tid*DD + bid] = s;
    } else if (bid == 64) {
        if (tid < DD) {
            float s = bpq[tid];
            #pragma unroll
            for (int d = 0; d < DD; d++) s = fmaf(wpq[tid*DD + d], b_out[d], s);
            g_bc[tid] = s;
        }
        if (tid == 0) g_losssum = 0.f;
    } else {
        for (int k = tid; k < KCB; k += 128) {
            float s = 0.f;
            #pragma unroll
            for (int d = 0; d < DD; d++) { float c = cb[k*DD + d]; s = fmaf(c, c, s); }
            g_cnorm[k] = s; g_hist[k] = 0;
        }
    }
}

// ---- K=4 S=2 conv + bias + relu (R9-proven: 16-ci, 2-stage, 1 bar/chunk, 3 blk) ----
#define S2_WC (16*4*64)
#define S2_XC (16*264)
__global__ void __launch_bounds__(256,3) convS2_k(
    const float* __restrict__ in, const float* __restrict__ w,
    const float* __restrict__ bias, float* __restrict__ out,
    int Cin, int Tin, int Cout, int Tout)
{
    extern __shared__ float sm[];
    float* swb = sm; float* sxb = sm + 2*S2_WC;
    const int tid = threadIdx.x, tslot = tid&15, cslot = tid>>4;
    const int t0 = blockIdx.x*128, co0 = blockIdx.y*64, b = blockIdx.z;

    float acc[4][8];
    #pragma unroll
    for (int c = 0; c < 4; c++) {
        float bv = bias[co0 + cslot*4 + c];
        #pragma unroll
        for (int j = 0; j < 8; j++) acc[c][j] = bv;
    }
    auto load_chunk = [&](int cc, int buf) {
        float* sx = sxb + buf*S2_XC;
        for (int idx = tid; idx < 16*66; idx += 256) {
            int ci = idx/66, q = idx - ci*66;
            int gb = 2*t0 - 4 + 4*q;
            bool ok = (gb >= 0) && (gb + 4 <= Tin);
            cpa16(&sx[ci*264 + 4*q], in + ((size_t)b*Cin + cc + ci)*Tin + (ok?gb:0), ok);
        }
        float* sw = swb + buf*S2_WC;
        for (int idx = tid; idx < 16*4*64; idx += 256) {
            int co = idx&63, r = idx>>6, ci = r>>2, k = r&3;
            cpa4(&sw[idx], &w[((size_t)(co0+co)*Cin + cc + ci)*4 + k]);
        }
    };
    const int nch = Cin>>4;
    load_chunk(0,0); cp_commit();
    for (int c = 0; c < nch; c++) {
        cp_wait0(); __syncthreads();
        if (c + 1 < nch) { load_chunk((c+1)<<4, (c+1)&1); cp_commit(); }
        const float* sx = sxb + (c&1)*S2_XC;
        const float* sw = swb + (c&1)*S2_WC;
        #pragma unroll 2
        for (int ci = 0; ci < 16; ci++) {
            float x[24];
            const float* xr = &sx[ci*264 + tslot*16];
            #pragma unroll
            for (int q = 0; q < 6; q++) { float4 v = *(const float4*)(xr+4*q); x[4*q]=v.x; x[4*q+1]=v.y; x[4*q+2]=v.z; x[4*q+3]=v.w; }
            float wv[4][4];
            #pragma unroll
            for (int k = 0; k < 4; k++) {
                float4 v = *(const float4*)&sw[(ci*4+k)*64 + cslot*4];
                wv[k][0]=v.x; wv[k][1]=v.y; wv[k][2]=v.z; wv[k][3]=v.w;
            }
            #pragma unroll
            for (int c4 = 0; c4 < 4; c4++)
                #pragma unroll
                for (int j = 0; j < 8; j++)
                    #pragma unroll
                    for (int k = 0; k < 4; k++)
                        acc[c4][j] = fmaf(x[2*j+3+k], wv[k][c4], acc[c4][j]);
        }
    }
    #pragma unroll
    for (int c = 0; c < 4; c++) {
        float4* op = (float4*)(out + ((size_t)b*Cout + co0 + cslot*4 + c)*Tout + t0 + tslot*8);
        op[0] = make_float4(fmaxf(acc[c][0],0.f), fmaxf(acc[c][1],0.f), fmaxf(acc[c][2],0.f), fmaxf(acc[c][3],0.f));
        op[1] = make_float4(fmaxf(acc[c][4],0.f), fmaxf(acc[c][5],0.f), fmaxf(acc[c][6],0.f), fmaxf(acc[c][7],0.f));
    }
}

// ---- K=3 S=1 conv (R9-proven: Cin=128, 16-ci, 3-stage, 1 bar/chunk) ----
#define K3_WC (16*3*64)
#define K3_XC (16*136)
template<bool RELU_IN, bool RELU_OUT, bool HAS_BIAS>
__global__ void __launch_bounds__(256,3) convK3_k(
    const float* __restrict__ in, const float* __restrict__ w,
    const float* __restrict__ bias, float* __restrict__ out)
{
    extern __shared__ float sm[];
    float* swb = sm; float* sxb = sm + 3*K3_WC;
    const int tid = threadIdx.x, tslot = tid&15, cslot = tid>>4;
    const int t0 = blockIdx.x*128, co0 = blockIdx.y*64, b = blockIdx.z;
    const int Cout = gridDim.y*64;
    const int Cin = H;

    float acc[4][8];
    #pragma unroll
    for (int c = 0; c < 4; c++) {
        float bv = HAS_BIAS ? bias[co0 + cslot*4 + c] : 0.f;
        #pragma unroll
        for (int j = 0; j < 8; j++) acc[c][j] = bv;
    }
    auto load_chunk = [&](int cc, int buf) {
        float* sx = sxb + buf*K3_XC;
        for (int idx = tid; idx < 16*34; idx += 256) {
            int ci = idx/34, q = idx - ci*34;
            int gb = t0 - 4 + 4*q;
            bool ok = (gb >= 0) && (gb + 4 <= T2);
            cpa16(&sx[ci*136 + 4*q], in + ((size_t)b*Cin + cc + ci)*T2 + (ok?gb:0), ok);
        }
        float* sw = swb + buf*K3_WC;
        for (int idx = tid; idx < 16*3*64; idx += 256) {
            int co = idx&63, r = idx>>6, ci = r/3, k = r - ci*3;
            cpa4(&sw[idx], &w[((size_t)(co0+co)*Cin + cc + ci)*3 + k]);
        }
    };
    const int nch = Cin>>4;
    load_chunk(0,0);  cp_commit();
    load_chunk(16,1); cp_commit();
    #pragma unroll 1
    for (int c = 0; c < nch; c++) {
        if (c == nch-1) cp_wait0(); else cp_wait1();
        __syncthreads();
        if (c + 2 < nch) { load_chunk((c+2)<<4, (c+2)%3); cp_commit(); }
        const float* sx = sxb + (c%3)*K3_XC;
        const float* sw = swb + (c%3)*K3_WC;
        #pragma unroll 2
        for (int ci = 0; ci < 16; ci++) {
            float x[16];
            const float* xr = &sx[ci*136 + tslot*8];
            #pragma unroll
            for (int q = 0; q < 4; q++) { float4 v = *(const float4*)(xr+4*q); x[4*q]=v.x; x[4*q+1]=v.y; x[4*q+2]=v.z; x[4*q+3]=v.w; }
            if (RELU_IN) {
                #pragma unroll
                for (int i = 0; i < 16; i++) x[i] = fmaxf(x[i], 0.f);
            }
            float wv[3][4];
            #pragma unroll
            for (int k = 0; k < 3; k++) {
                float4 v = *(const float4*)&sw[(ci*3+k)*64 + cslot*4];
                wv[k][0]=v.x; wv[k][1]=v.y; wv[k][2]=v.z; wv[k][3]=v.w;
            }
            #pragma unroll
            for (int c4 = 0; c4 < 4; c4++)
                #pragma unroll
                for (int j = 0; j < 8; j++)
                    #pragma unroll
                    for (int k = 0; k < 3; k++)
                        acc[c4][j] = fmaf(x[j+3+k], wv[k][c4], acc[c4][j]);
        }
    }
    #pragma unroll
    for (int c = 0; c < 4; c++) {
        float v[8];
        #pragma unroll
        for (int j = 0; j < 8; j++) v[j] = RELU_OUT ? fmaxf(acc[c][j],0.f) : acc[c][j];
        float4* op = (float4*)(out + ((size_t)b*Cout + co0 + cslot*4 + c)*T2 + t0 + tslot*8);
        op[0] = make_float4(v[0], v[1], v[2], v[3]);
        op[1] = make_float4(v[4], v[5], v[6], v[7]);
    }
}

// ---- fused residual block, restructured: 256 thr, mid in smem, 75.8KB -> 3 blk/SM ----
// phase B: mid = relu(conv3(relu(in))), 16-ci chunks 2-stage; phase C: out = in + wb@mid.
#define RN_STA (64*132)              // mid tile [mid][132]
#define RN_WC  (16*3*64)
#define RN_XC  (16*136)
#define RN_STG (RN_WC + RN_XC)       // 5248 per stage
__global__ void __launch_bounds__(256) resblock_k(
    const float* __restrict__ in, const float* __restrict__ wa,
    const float* __restrict__ wb, float* __restrict__ out)
{
    extern __shared__ float s[];
    float* sta = s;                  // [64][132]
    float* pb  = s + RN_STA;         // 2 stages of (W then X); later aliased by wb [mid][132]
    const int tid = threadIdx.x, tslot = tid&15, cslot = tid>>4;
    const int t0 = blockIdx.x*128, b = blockIdx.z;

    auto load_chunk = [&](int cc, int buf) {
        float* sw = pb + buf*RN_STG;
        float* sx = sw + RN_WC;
        for (int idx = tid; idx < 16*34; idx += 256) {
            int ci = idx/34, q = idx - ci*34;
            int gb = t0 - 4 + 4*q;
            bool ok = (gb >= 0) && (gb + 4 <= T2);
            cpa16(&sx[ci*136 + 4*q], in + ((size_t)b*H + cc + ci)*T2 + (ok?gb:0), ok);
        }
        for (int idx = tid; idx < 16*3*64; idx += 256) {
            int mid = idx&63, r = idx>>6, ci = r/3, k = r - ci*3;
            cpa4(&sw[idx], &wa[((size_t)mid*H + cc + ci)*3 + k]);
        }
    };

    // phase B: thread = 4 mid x 8 t
    {
        float acc[4][8];
        #pragma unroll
        for (int c = 0; c < 4; c++)
            #pragma unroll
            for (int j = 0; j < 8; j++) acc[c][j] = 0.f;
        load_chunk(0,0); cp_commit();
        for (int ch = 0; ch < 8; ch++) {
            cp_wait0(); __syncthreads();
            if (ch + 1 < 8) { load_chunk((ch+1)*16, (ch+1)&1); cp_commit(); }
            const float* sw = pb + (ch&1)*RN_STG;
            const float* sx = sw + RN_WC;
            #pragma unroll 2
            for (int ci = 0; ci < 16; ci++) {
                float x[16];
                const float* xr = &sx[ci*136 + tslot*8];
                #pragma unroll
                for (int q = 0; q < 4; q++) { float4 v = *(const float4*)(xr+4*q); x[4*q]=v.x; x[4*q+1]=v.y; x[4*q+2]=v.z; x[4*q+3]=v.w; }
                #pragma unroll
                for (int i = 0; i < 16; i++) x[i] = fmaxf(x[i], 0.f);
                float wv[3][4];
                #pragma unroll
                for (int k = 0; k < 3; k++) {
                    float4 v = *(const float4*)&sw[(ci*3+k)*64 + cslot*4];
                    wv[k][0]=v.x; wv[k][1]=v.y; wv[k][2]=v.z; wv[k][3]=v.w;
                }
                #pragma unroll
                for (int c4 = 0; c4 < 4; c4++)
                    #pragma unroll
                    for (int j = 0; j < 8; j++)
                        #pragma unroll
                        for (int k = 0; k < 3; k++)
                            acc[c4][j] = fmaf(x[j+3+k], wv[k][c4], acc[c4][j]);
            }
        }
        __syncthreads();
        #pragma unroll
        for (int c = 0; c < 4; c++) {
            float* d = &sta[(cslot*4 + c)*132 + tslot*8];
            #pragma unroll
            for (int jp = 0; jp < 4; jp++)
                *(float2*)(d + 2*jp) = make_float2(fmaxf(acc[c][2*jp],0.f), fmaxf(acc[c][2*jp+1],0.f));
        }
    }
    __syncthreads();

    // wb -> alias over pb: [mid][132 co]
    float* wbs = pb;
    for (int idx = tid; idx < H*RH; idx += 256) {
        int co = idx>>6, mid = idx&63;
        wbs[mid*132 + co] = wb[idx];
    }
    __syncthreads();

    // phase C: two co-halves, thread = 4 co x 8 t each
    #pragma unroll 1
    for (int coh = 0; coh < 2; coh++) {
        float acc[4][8];
        #pragma unroll
        for (int c = 0; c < 4; c++)
            #pragma unroll
            for (int j = 0; j < 8; j++) acc[c][j] = 0.f;
        #pragma unroll 2
        for (int mid = 0; mid < RH; mid++) {
            float x[8];
            const float* xr = &sta[mid*132 + tslot*8];
            { float4 v = *(const float4*)(xr);   x[0]=v.x; x[1]=v.y; x[2]=v.z; x[3]=v.w; }
            { float4 v = *(const float4*)(xr+4); x[4]=v.x; x[5]=v.y; x[6]=v.z; x[7]=v.w; }
            float4 wv = *(const float4*)&wbs[mid*132 + coh*64 + cslot*4];
            float wc[4] = {wv.x, wv.y, wv.z, wv.w};
            #pragma unroll
            for (int c = 0; c < 4; c++)
                #pragma unroll
                for (int j = 0; j < 8; j++) acc[c][j] = fmaf(x[j], wc[c], acc[c][j]);
        }
        #pragma unroll
        for (int c = 0; c < 4; c++) {
            int co = coh*64 + cslot*4 + c;
            const float4* ip = (const float4*)(in + ((size_t)b*H + co)*T2 + t0 + tslot*8);
            float4 r0 = ip[0], r1 = ip[1];
            float4* op = (float4*)(out + ((size_t)b*H + co)*T2 + t0 + tslot*8);
            op[0] = make_float4(r0.x+acc[c][0], r0.y+acc[c][1], r0.z+acc[c][2], r0.w+acc[c][3]);
            op[1] = make_float4(r1.x+acc[c][4], r1.y+acc[c][5], r1.z+acc[c][6], r1.w+acc[c][7]);
        }
    }
}

// ---- fused relu + Wc + transpose -> z_e (R10-proven) ----
#define Z_SH (128*136)
#define Z_SW (128*64)
__global__ void __launch_bounds__(256) zfused_k(const float* __restrict__ h, float* __restrict__ ze)
{
    extern __shared__ float s[];
    float* sh = s; float* sw = s + Z_SH;
    const int tid = threadIdx.x, tslot = tid&15, cslot = tid>>4;
    const int t0 = blockIdx.x*128, b = blockIdx.z;

    for (int idx = tid; idx < 128*128; idx += 256) {
        int ci = idx>>7, t = idx&127;
        sh[ci*136 + t] = fmaxf(h[((size_t)b*H + ci)*T2 + t0 + t], 0.f);
    }
    for (int i = tid; i < (H*DD)/4; i += 256) ((float4*)sw)[i] = ((const float4*)g_WcT)[i];
    __syncthreads();

    float acc[4][8];
    #pragma unroll
    for (int c = 0; c < 4; c++) {
        float bv = g_bc[cslot*4 + c];
        #pragma unroll
        for (int j = 0; j < 8; j++) acc[c][j] = bv;
    }
    #pragma unroll 2
    for (int ch = 0; ch < H; ch++) {
        float x[8];
        const float* xr = &sh[ch*136 + tslot*8];
        { float4 v = *(const float4*)(xr);   x[0]=v.x; x[1]=v.y; x[2]=v.z; x[3]=v.w; }
        { float4 v = *(const float4*)(xr+4); x[4]=v.x; x[5]=v.y; x[6]=v.z; x[7]=v.w; }
        float4 wv = *(const float4*)&sw[ch*64 + cslot*4];
        float wc[4] = {wv.x, wv.y, wv.z, wv.w};
        #pragma unroll
        for (int c = 0; c < 4; c++)
            #pragma unroll
            for (int j = 0; j < 8; j++) acc[c][j] = fmaf(x[j], wc[c], acc[c][j]);
    }
    #pragma unroll
    for (int j = 0; j < 8; j++) {
        size_t n = (size_t)b*T2 + t0 + tslot*8 + j;
        float2* op = (float2*)(ze + n*DD + cslot*4);
        op[0] = make_float2(acc[0][j], acc[1][j]);
        op[1] = make_float2(acc[2][j], acc[3][j]);
    }
}

// ---- VQ distance-GEMM (R10-proven) ----
#define VQ_SZ (64*136)
#define VQ_SC (64*136)
__global__ void __launch_bounds__(256) vqgemm_k(
    const float* __restrict__ ze, const float* __restrict__ cb,
    float* __restrict__ zq, float* __restrict__ enc, float* __restrict__ idxout)
{
    extern __shared__ float s[];
    float* szeT = s; float* scb = s + VQ_SZ; float* scn = scb + VQ_SC;
    int* sbk = (int*)(scn + KCB);
    const int tid = threadIdx.x, n0 = blockIdx.x*128, nslot = tid>>4, kslot = tid&15;

    for (int idx = tid; idx < 128*DD; idx += 256) {
        int n = idx>>6, d = idx&63;
        szeT[d*136 + n] = ze[(size_t)(n0+n)*DD + d];
    }
    for (int k = tid; k < KCB; k += 256) scn[k] = g_cnorm[k];
    __syncthreads();

    float best[8]; int bk[8];
    #pragma unroll
    for (int i = 0; i < 8; i++) { best[i] = 3.4e38f; bk[i] = 0; }

    for (int kc = 0; kc < KCB; kc += 128) {
        for (int idx = tid; idx < 128*DD; idx += 256) {
            int kk = idx>>6, d = idx&63;
            scb[d*136 + kk] = cb[(size_t)(kc+kk)*DD + d];
        }
        __syncthreads();
        float acc[8][8];
        #pragma unroll
        for (int i = 0; i < 8; i++)
            #pragma unroll
            for (int j = 0; j < 8; j++) acc[i][j] = 0.f;
        #pragma unroll 2
        for (int d = 0; d < DD; d++) {
            float fz[8], fc[8];
            const float* zr = &szeT[d*136 + nslot*8];
            { float4 v = *(const float4*)(zr);   fz[0]=v.x; fz[1]=v.y; fz[2]=v.z; fz[3]=v.w; }
            { float4 v = *(const float4*)(zr+4); fz[4]=v.x; fz[5]=v.y; fz[6]=v.z; fz[7]=v.w; }
            const float* cr = &scb[d*136 + kslot*8];
            { float4 v = *(const float4*)(cr);   fc[0]=v.x; fc[1]=v.y; fc[2]=v.z; fc[3]=v.w; }
            { float4 v = *(const float4*)(cr+4); fc[4]=v.x; fc[5]=v.y; fc[6]=v.z; fc[7]=v.w; }
            #pragma unroll
            for (int i = 0; i < 8; i++)
                #pragma unroll
                for (int j = 0; j < 8; j++) acc[i][j] = fmaf(fz[i], fc[j], acc[i][j]);
        }
        #pragma unroll
        for (int j = 0; j < 8; j++) {
            int kg = kc + kslot*8 + j;
            float cn = scn[kg];
            #pragma unroll
            for (int i = 0; i < 8; i++) {
                float dist = cn - 2.f*acc[i][j];
                if (dist < best[i]) { best[i] = dist; bk[i] = kg; }
            }
        }
        __syncthreads();
    }
    #pragma unroll
    for (int off = 8; off > 0; off >>= 1) {
        #pragma unroll
        for (int i = 0; i < 8; i++) {
            float ob = __shfl_down_sync(0xffffffffu, best[i], off, 16);
            int ok = __shfl_down_sync(0xffffffffu, bk[i], off, 16);
            if (ob < best[i] || (ob == best[i] && ok < bk[i])) { best[i] = ob; bk[i] = ok; }
        }
    }
    if (kslot == 0)
        #pragma unroll
        for (int i = 0; i < 8; i++) sbk[nslot*8 + i] = bk[i];
    __syncthreads();

    float part = 0.f;
    for (int idx = tid; idx < 128*DD; idx += 256) {
        int nl = idx>>6, d = idx&63;
        int kk = sbk[nl];
        float c = cb[(size_t)kk*DD + d];
        float f = szeT[d*136 + nl];
        zq[(size_t)(n0+nl)*DD + d] = c;
        float df = c - f;
        part = fmaf(df, df, part);
    }
    const float2 z2 = make_float2(0.f, 0.f);
    for (int r = 0; r < 128; r++) ((float2*)(enc + (size_t)(n0+r)*KCB))[tid] = z2;
    __syncthreads();
    if (tid < 128) {
        int kk = sbk[tid];
        idxout[n0 + tid] = (float)kk;
        enc[(size_t)(n0+tid)*KCB + kk] = 1.f;
        atomicAdd(&g_hist[kk], 1);
    }
    #pragma unroll
    for (int o = 16; o > 0; o >>= 1) part += __shfl_down_sync(0xffffffffu, part, o);
    __shared__ float wsum[8];
    if ((tid&31) == 0) wsum[tid>>5] = part;
    __syncthreads();
    if (tid < 8) {
        float v = wsum[tid];
        #pragma unroll
        for (int o = 4; o > 0; o >>= 1) v += __shfl_down_sync(0xffu, v, o);
        if (tid == 0) atomicAdd(&g_losssum, v);
    }
}

__global__ void fin_k(float* __restrict__ loss_out, float* __restrict__ perp_out)
{
    __shared__ float red[512];
    const int k = threadIdx.x;
    float p = (float)g_hist[k]*(1.0f/(float)NN);
    red[k] = p*logf(p + 1e-10f);
    __syncthreads();
    for (int s2 = 256; s2 > 0; s2 >>= 1) { if (k < s2) red[k] += red[k + s2]; __syncthreads(); }
    if (k == 0) {
        perp_out[0] = expf(-red[0]);
        loss_out[0] = 1.25f*g_losssum/(float)((size_t)NN*DD);
    }
}

extern "C" void kernel_launch(void* const* d_in, const int* in_sizes, int n_in,
                              void* d_out, int out_size)
{
    const float* x     = (const float*)d_in[0];
    const float* w1    = (const float*)d_in[1];
    const float* b1    = (const float*)d_in[2];
    const float* w2    = (const float*)d_in[3];
    const float* b2    = (const float*)d_in[4];
    const float* w3    = (const float*)d_in[5];
    const float* b3    = (const float*)d_in[6];
    const float* r0w1  = (const float*)d_in[7];
    const float* r0w2  = (const float*)d_in[8];
    const float* r1w1  = (const float*)d_in[9];
    const float* r1w2  = (const float*)d_in[10];
    const float* w_out = (const float*)d_in[11];
    const float* b_out = (const float*)d_in[12];
    const float* wpq   = (const float*)d_in[13];
    const float* bpq   = (const float*)d_in[14];
    const float* cb    = (const float*)d_in[15];

    float* outp = (float*)d_out;
    const size_t NZ = (size_t)NN*DD;
    float* o_loss = outp;
    float* o_zq   = outp + 1;
    float* o_perp = outp + 1 + NZ;
    float* o_ze   = outp + 2 + NZ;
    float* o_enc  = outp + 2 + 2*NZ;
    float* o_idx  = outp + 2 + 2*NZ + (size_t)NN*KCB;

    auto* kConv3 = convK3_k<false, false, true>;

    const int smem_S2 = 2*(S2_WC + S2_XC)*4;        // 66,560
    const int smem_K3 = 3*(K3_WC + K3_XC)*4;        // 62,976
    const int smem_RB = (RN_STA + 2*RN_STG)*4;      // 75,776
    const int z_smem  = (Z_SH + Z_SW)*4;            // 102,400
    const int vq_smem = (VQ_SZ + VQ_SC + KCB)*4 + 128*4;

    static int attr_done = 0;
    if (!attr_done) {
        cudaFuncSetAttribute(convS2_k,   cudaFuncAttributeMaxDynamicSharedMemorySize, smem_S2);
        cudaFuncSetAttribute(kConv3,     cudaFuncAttributeMaxDynamicSharedMemorySize, smem_K3);
        cudaFuncSetAttribute(resblock_k, cudaFuncAttributeMaxDynamicSharedMemorySize, smem_RB);
        cudaFuncSetAttribute(zfused_k,   cudaFuncAttributeMaxDynamicSharedMemorySize, z_smem);
        cudaFuncSetAttribute(vqgemm_k,   cudaFuncAttributeMaxDynamicSharedMemorySize, vq_smem);
        attr_done = 1;
    }

    precompute_k<<<66, 128>>>(wpq, w_out, b_out, bpq, cb);

    convS2_k<<<dim3(16, 1, BB), 256, smem_S2>>>(x,    w1, b1, g_h1, CIN, T0, HH, T1);
    convS2_k<<<dim3(8,  2, BB), 256, smem_S2>>>(g_h1, w2, b2, g_h2, HH,  T1, H,  T2);
    kConv3<<<dim3(8, 2, BB), 256, smem_K3>>>(g_h2, w3, b3, g_h3);

    resblock_k<<<dim3(8, 1, BB), 256, smem_RB>>>(g_h3, r0w1, r0w2, g_h2);
    resblock_k<<<dim3(8, 1, BB), 256, smem_RB>>>(g_h2, r1w1, r1w2, g_h3);

    zfused_k<<<dim3(8, 1, BB), 256, z_smem>>>(g_h3, o_ze);

    vqgemm_k<<<NN/128, 256, vq_smem>>>(o_ze, cb, o_zq, o_enc, o_idx);

    fin_k<<<1, 512>>>(o_loss, o_perp);
}